// round 3
// baseline (speedup 1.0000x reference)
#include <cuda_runtime.h>
#include <cstdint>

// SpatialTransformer bilinear flow warp.
// src:  [B,H,W,1] f32,  flow: [B,H,W,2] f32,  out: [B,H,W,1] f32
// B=32, H=768, W=768.
//
// Layout: 32x32 pixel tile per block (256 threads).
//   lane -> x within tile (warp = 32 consecutive x -> coalesced gathers)
//   warp -> 4-row vertical strip (L1 reuse of bilinear row halo)
//
// This version is explicitly phase-batched to maximize MLP:
//   phase 1: 4 flow loads (independent)
//   phase 2: all index/weight math
//   phase 3: 16 gathers issued back-to-back (MLP=16)
//   phase 4: FMAs + 4 stores

#define BB 32
#define HH 768
#define WW 768
#define HW (HH * WW)

__global__ __launch_bounds__(256) void warp_kernel(
    const float* __restrict__ src,
    const float* __restrict__ flow,
    float* __restrict__ out)
{
    const int tx = threadIdx.x;
    const int xg = blockIdx.x * 32 + (tx & 31);
    const int yb = blockIdx.y * 32 + (tx >> 5) * 4;
    const int b  = blockIdx.z;

    const float* img  = src + b * HW;
    const int    pix0 = (b * HH + yb) * WW + xg;
    const float  xgf  = (float)xg;

    // ---- phase 1: all flow loads up front (4 independent LDG.64) ----
    float2 f[4];
    #pragma unroll
    for (int r = 0; r < 4; r++)
        f[r] = *reinterpret_cast<const float2*>(flow + (size_t)(pix0 + r * WW) * 2);

    // ---- phase 2: all weights + addresses ----
    float wa[4], wb[4], wc[4], wd[4];
    int   a00[4], a01[4], a10[4], a11[4];

    #pragma unroll
    for (int r = 0; r < 4; r++) {
        const float gx = xgf + f[r].x;
        const float gy = (float)(yb + r) + f[r].y;

        const float x0f = floorf(gx);
        const float y0f = floorf(gy);
        const float x1f = x0f + 1.0f;
        const float y1f = y0f + 1.0f;

        const float dx1 = x1f - gx;
        const float dx0 = gx - x0f;
        const float dy1 = y1f - gy;
        const float dy0 = gy - y0f;

        wa[r] = dx1 * dy1;
        wb[r] = dx0 * dy1;
        wc[r] = dx1 * dy0;
        wd[r] = dx0 * dy0;

        const int xi0 = (int)fminf(fmaxf(x0f, 0.0f), (float)(WW - 1));
        const int xi1 = (int)fminf(fmaxf(x1f, 0.0f), (float)(WW - 1));
        const int yi0 = (int)fminf(fmaxf(y0f, 0.0f), (float)(HH - 1));
        const int yi1 = (int)fminf(fmaxf(y1f, 0.0f), (float)(HH - 1));

        const int r0 = yi0 * WW;
        const int r1 = yi1 * WW;
        a00[r] = r0 + xi0;
        a01[r] = r0 + xi1;
        a10[r] = r1 + xi0;
        a11[r] = r1 + xi1;
    }

    // ---- phase 3: all 16 gathers back-to-back (max MLP) ----
    float va[4], vb[4], vc[4], vd[4];
    #pragma unroll
    for (int r = 0; r < 4; r++) va[r] = __ldg(img + a00[r]);
    #pragma unroll
    for (int r = 0; r < 4; r++) vb[r] = __ldg(img + a01[r]);
    #pragma unroll
    for (int r = 0; r < 4; r++) vc[r] = __ldg(img + a10[r]);
    #pragma unroll
    for (int r = 0; r < 4; r++) vd[r] = __ldg(img + a11[r]);

    // ---- phase 4: combine + store ----
    #pragma unroll
    for (int r = 0; r < 4; r++) {
        out[pix0 + r * WW] =
            wa[r] * va[r] + wb[r] * vb[r] + wc[r] * vc[r] + wd[r] * vd[r];
    }
}

extern "C" void kernel_launch(void* const* d_in, const int* in_sizes, int n_in,
                              void* d_out, int out_size)
{
    const float* src  = (const float*)d_in[0];
    const float* flow = (const float*)d_in[1];
    float* out = (float*)d_out;

    dim3 grid(WW / 32, HH / 32, BB);   // (24, 24, 32)
    warp_kernel<<<grid, 256>>>(src, flow, out);
}